// round 4
// baseline (speedup 1.0000x reference)
#include <cuda_runtime.h>
#include <cuda_bf16.h>

// ForwardKinematics: B=524288, NA=7 joints, NJ=8 transforms.
// out[n] = M0*M1*...*M6*F7, Mi = Fi * [[R(theta_i, a_i), 0],[0,1]]
// Rodrigues: R = I + s*K + (1-c)*K^2, K^2 = a a^T - I (unit axis)
// => rot(Mi) = A_i + s*(A_i K_i) + (1-c)*(A_i a a^T - A_i), trans(Mi) = t_i
//
// R3: same as R2 (smem-staged coalesced input+output) with 16B-aligned
// shared staging arrays (R2's float4 casts trapped: arrays landed at
// offset 888 = 8 mod 16).

#define NACT 7
#define THREADS 256
#define OUT_STRIDE_F 20   // 16 payload + 4 pad floats per element (5 float4s)

__global__ __launch_bounds__(THREADS)
void fk_kernel(const float* __restrict__ jp,    // (B,7)
               const float* __restrict__ ft,    // (8,4,4)
               const float* __restrict__ axes,  // (7,3)
               float* __restrict__ out,         // (B,4,4)
               int n)
{
    // 16B-aligned staging arrays FIRST, scalars after.
    __shared__ alignas(16) float sout[THREADS * OUT_STRIDE_F];   // 5120 floats
    __shared__ alignas(16) float sin_stage[THREADS * NACT];      // 1792 floats
    __shared__ float sj[NACT][30];          // A[9], A@K[9], A@(aa^T-I)[9], t[3]
    __shared__ float sF7[12];

    const int tid = threadIdx.x;

    // ---- per-joint constants (once per block) ----
    if (tid < NACT) {
        const float* F = ft + tid * 16;
        float A[9];
        #pragma unroll
        for (int r = 0; r < 3; r++)
            #pragma unroll
            for (int c = 0; c < 3; c++)
                A[r * 3 + c] = F[r * 4 + c];
        const float ax = axes[tid * 3 + 0];
        const float ay = axes[tid * 3 + 1];
        const float az = axes[tid * 3 + 2];
        float* d = sj[tid];
        #pragma unroll
        for (int k = 0; k < 9; k++) d[k] = A[k];
        #pragma unroll
        for (int r = 0; r < 3; r++) {
            d[9 + r * 3 + 0] = A[r * 3 + 1] * az - A[r * 3 + 2] * ay;
            d[9 + r * 3 + 1] = A[r * 3 + 2] * ax - A[r * 3 + 0] * az;
            d[9 + r * 3 + 2] = A[r * 3 + 0] * ay - A[r * 3 + 1] * ax;
        }
        #pragma unroll
        for (int r = 0; r < 3; r++) {
            float dp = A[r * 3 + 0] * ax + A[r * 3 + 1] * ay + A[r * 3 + 2] * az;
            d[18 + r * 3 + 0] = dp * ax - A[r * 3 + 0];
            d[18 + r * 3 + 1] = dp * ay - A[r * 3 + 1];
            d[18 + r * 3 + 2] = dp * az - A[r * 3 + 2];
        }
        d[27] = F[3]; d[28] = F[7]; d[29] = F[11];
    }
    if (tid < 12) sF7[tid] = ft[7 * 16 + tid];

    // ---- coalesced input stage: 1792 floats = 448 float4 ----
    {
        const long long base_f = (long long)blockIdx.x * (THREADS * NACT);
        const long long total_f = (long long)n * NACT;
        #pragma unroll
        for (int j = 0; j < 2; j++) {
            int f4 = j * THREADS + tid;
            if (f4 < (THREADS * NACT) / 4) {
                long long g = base_f + (long long)f4 * 4;
                float4 v;
                if (g + 3 < total_f) {
                    v = *reinterpret_cast<const float4*>(jp + g);
                } else {
                    v.x = (g + 0 < total_f) ? jp[g + 0] : 0.0f;
                    v.y = (g + 1 < total_f) ? jp[g + 1] : 0.0f;
                    v.z = (g + 2 < total_f) ? jp[g + 2] : 0.0f;
                    v.w = (g + 3 < total_f) ? jp[g + 3] : 0.0f;
                }
                *reinterpret_cast<float4*>(sin_stage + f4 * 4) = v;
            }
        }
    }
    __syncthreads();

    float th[NACT];
    #pragma unroll
    for (int i = 0; i < NACT; i++) th[i] = sin_stage[tid * NACT + i];  // stride 7: conflict-free

    float Tr[9], Tt[3];

    // joint 0: T = M0
    {
        float s, c;
        __sincosf(th[0], &s, &c);
        const float o = 1.0f - c;
        const float* d = sj[0];
        #pragma unroll
        for (int k = 0; k < 9; k++)
            Tr[k] = d[k] + s * d[9 + k] + o * d[18 + k];
        Tt[0] = d[27]; Tt[1] = d[28]; Tt[2] = d[29];
    }

    // joints 1..6: T = T @ Mi
    #pragma unroll
    for (int i = 1; i < NACT; i++) {
        float s, c;
        __sincosf(th[i], &s, &c);
        const float o = 1.0f - c;
        const float* d = sj[i];
        float M[9];
        #pragma unroll
        for (int k = 0; k < 9; k++)
            M[k] = d[k] + s * d[9 + k] + o * d[18 + k];

        float R[9];
        #pragma unroll
        for (int r = 0; r < 3; r++)
            #pragma unroll
            for (int c2 = 0; c2 < 3; c2++)
                R[r * 3 + c2] = Tr[r * 3 + 0] * M[0 + c2]
                              + Tr[r * 3 + 1] * M[3 + c2]
                              + Tr[r * 3 + 2] * M[6 + c2];

        const float tx = d[27], ty = d[28], tz = d[29];
        #pragma unroll
        for (int r = 0; r < 3; r++)
            Tt[r] += Tr[r * 3 + 0] * tx + Tr[r * 3 + 1] * ty + Tr[r * 3 + 2] * tz;

        #pragma unroll
        for (int k = 0; k < 9; k++) Tr[k] = R[k];
    }

    // final: T = T @ F7
    float Rr[9], Ot[3];
    #pragma unroll
    for (int r = 0; r < 3; r++) {
        #pragma unroll
        for (int c2 = 0; c2 < 3; c2++)
            Rr[r * 3 + c2] = Tr[r * 3 + 0] * sF7[0 + c2]
                           + Tr[r * 3 + 1] * sF7[4 + c2]
                           + Tr[r * 3 + 2] * sF7[8 + c2];
        Ot[r] = Tt[r] + Tr[r * 3 + 0] * sF7[3]
                      + Tr[r * 3 + 1] * sF7[7]
                      + Tr[r * 3 + 2] * sF7[11];
    }

    // ---- stage results: stride 5 float4 (odd -> conflict-free STS.128) ----
    {
        float4* s4 = reinterpret_cast<float4*>(sout) + tid * (OUT_STRIDE_F / 4);
        s4[0] = make_float4(Rr[0], Rr[1], Rr[2], Ot[0]);
        s4[1] = make_float4(Rr[3], Rr[4], Rr[5], Ot[1]);
        s4[2] = make_float4(Rr[6], Rr[7], Rr[8], Ot[2]);
        s4[3] = make_float4(0.0f, 0.0f, 0.0f, 1.0f);
    }
    __syncthreads();

    // ---- coalesced output: 1024 float4 per block ----
    {
        const float4* s4 = reinterpret_cast<const float4*>(sout);
        float4* o4 = reinterpret_cast<float4*>(out) + (long long)blockIdx.x * (THREADS * 4);
        const long long total_f4 = (long long)n * 4;
        const long long base_f4 = (long long)blockIdx.x * (THREADS * 4);
        if (base_f4 + THREADS * 4 <= total_f4) {
            // full block fast path (always taken for B=524288)
            #pragma unroll
            for (int j = 0; j < 4; j++) {
                int f4 = j * THREADS + tid;
                int e = f4 >> 2;
                int r = f4 & 3;
                o4[f4] = s4[e * (OUT_STRIDE_F / 4) + r];
            }
        } else {
            #pragma unroll
            for (int j = 0; j < 4; j++) {
                int f4 = j * THREADS + tid;
                int e = f4 >> 2;
                int r = f4 & 3;
                if (base_f4 + f4 < total_f4)
                    o4[f4] = s4[e * (OUT_STRIDE_F / 4) + r];
            }
        }
    }
}

extern "C" void kernel_launch(void* const* d_in, const int* in_sizes, int n_in,
                              void* d_out, int out_size) {
    const float* jp   = (const float*)d_in[0];  // joint_positions (B,7)
    const float* ft   = (const float*)d_in[1];  // fixed_transforms (8,4,4)
    const float* axes = (const float*)d_in[2];  // joint_axes (7,3)
    float* out = (float*)d_out;
    const int n = in_sizes[0] / NACT;
    const int blocks = (n + THREADS - 1) / THREADS;
    fk_kernel<<<blocks, THREADS>>>(jp, ft, axes, out, n);
}

// round 5
// speedup vs baseline: 1.1050x; 1.1050x over previous
#include <cuda_runtime.h>
#include <cuda_bf16.h>

// ForwardKinematics: B=524288, NA=7 joints, NJ=8 transforms.
// out[n] = M0*...*M6*F7, Mi = Fi*[[R(theta_i,a_i),0],[0,1]]
// rot(Mi) = A_i + sin*(A_i K_i) + (1-cos)*(A_i(aa^T) - A_i); trans(Mi)=t_i.
//
// R5: issue-bound kernel -> halve math instruction count with packed
// fma.rn.f32x2 (FFMA2). Each thread computes TWO batch elements (g, g+n/2)
// packed lane-wise in 64-bit f32x2 registers. Per-joint constants are
// pre-splatted to float2(v,v) in smem so broadcast LDS.64 feeds FFMA2
// directly. Memory access pattern per element identical to the R1 baseline.

#define NACT 7
#define THREADS 256

typedef unsigned long long u64;

__device__ __forceinline__ u64 fma2(u64 a, u64 b, u64 c) {
    u64 d; asm("fma.rn.f32x2 %0, %1, %2, %3;" : "=l"(d) : "l"(a), "l"(b), "l"(c)); return d;
}
__device__ __forceinline__ u64 mul2(u64 a, u64 b) {
    u64 d; asm("mul.rn.f32x2 %0, %1, %2;" : "=l"(d) : "l"(a), "l"(b)); return d;
}
__device__ __forceinline__ u64 pack2(float lo, float hi) {
    u64 d; asm("mov.b64 %0, {%1, %2};" : "=l"(d) : "f"(lo), "f"(hi)); return d;
}
__device__ __forceinline__ float2 unpack2(u64 v) {
    float lo, hi; asm("mov.b64 {%0, %1}, %2;" : "=f"(lo), "=f"(hi) : "l"(v));
    return make_float2(lo, hi);
}

__global__ __launch_bounds__(THREADS)
void fk_kernel(const float* __restrict__ jp,    // (B,7)
               const float* __restrict__ ft,    // (8,4,4)
               const float* __restrict__ axes,  // (7,3)
               float* __restrict__ out,         // (B,4,4)
               int n)
{
    // splatted per-joint constants: A[9], A@K[9], A@(aa^T-I)[9], t[3] as float2(v,v)
    __shared__ alignas(16) float2 sj2[NACT][30];
    __shared__ alignas(16) float2 sF72[12];

    const int tid = threadIdx.x;

    if (tid < NACT) {
        const float* F = ft + tid * 16;
        float A[9];
        #pragma unroll
        for (int r = 0; r < 3; r++)
            #pragma unroll
            for (int c = 0; c < 3; c++)
                A[r * 3 + c] = F[r * 4 + c];
        const float ax = axes[tid * 3 + 0];
        const float ay = axes[tid * 3 + 1];
        const float az = axes[tid * 3 + 2];
        float2* d = sj2[tid];
        #pragma unroll
        for (int k = 0; k < 9; k++) d[k] = make_float2(A[k], A[k]);
        #pragma unroll
        for (int r = 0; r < 3; r++) {
            float b0 = A[r * 3 + 1] * az - A[r * 3 + 2] * ay;
            float b1 = A[r * 3 + 2] * ax - A[r * 3 + 0] * az;
            float b2 = A[r * 3 + 0] * ay - A[r * 3 + 1] * ax;
            d[9 + r * 3 + 0] = make_float2(b0, b0);
            d[9 + r * 3 + 1] = make_float2(b1, b1);
            d[9 + r * 3 + 2] = make_float2(b2, b2);
        }
        #pragma unroll
        for (int r = 0; r < 3; r++) {
            float dp = A[r * 3 + 0] * ax + A[r * 3 + 1] * ay + A[r * 3 + 2] * az;
            float c0 = dp * ax - A[r * 3 + 0];
            float c1 = dp * ay - A[r * 3 + 1];
            float c2 = dp * az - A[r * 3 + 2];
            d[18 + r * 3 + 0] = make_float2(c0, c0);
            d[18 + r * 3 + 1] = make_float2(c1, c1);
            d[18 + r * 3 + 2] = make_float2(c2, c2);
        }
        d[27] = make_float2(F[3],  F[3]);
        d[28] = make_float2(F[7],  F[7]);
        d[29] = make_float2(F[11], F[11]);
    }
    if (tid < 12) {
        float v = ft[7 * 16 + tid];
        sF72[tid] = make_float2(v, v);
    }
    __syncthreads();

    const int half = n >> 1;   // B = 524288, even
    const int g = blockIdx.x * THREADS + tid;
    if (g >= half) return;

    const float* p0 = jp + (size_t)g * NACT;
    const float* p1 = jp + (size_t)(g + half) * NACT;
    float th0[NACT], th1[NACT];
    #pragma unroll
    for (int i = 0; i < NACT; i++) th0[i] = p0[i];
    #pragma unroll
    for (int i = 0; i < NACT; i++) th1[i] = p1[i];

    const u64* j2 = reinterpret_cast<const u64*>(&sj2[0][0]);   // [joint*30 + k]
    const u64* F2 = reinterpret_cast<const u64*>(&sF72[0]);

    u64 Tr[9], Tt[3];

    // joint 0: T = M0
    {
        float s0, c0, s1, c1;
        __sincosf(th0[0], &s0, &c0);
        __sincosf(th1[0], &s1, &c1);
        u64 s2 = pack2(s0, s1);
        u64 o2 = pack2(1.0f - c0, 1.0f - c1);
        const u64* d = j2;
        #pragma unroll
        for (int k = 0; k < 9; k++)
            Tr[k] = fma2(o2, d[18 + k], fma2(s2, d[9 + k], d[k] /*A: fma a*1? */ ));
        // note: fma2(s2, B, A) computes s*B + A  -> then + o*C  : correct
        Tt[0] = d[27]; Tt[1] = d[28]; Tt[2] = d[29];
    }

    // joints 1..6: T = T @ Mi
    #pragma unroll
    for (int i = 1; i < NACT; i++) {
        float s0, c0, s1, c1;
        __sincosf(th0[i], &s0, &c0);
        __sincosf(th1[i], &s1, &c1);
        u64 s2 = pack2(s0, s1);
        u64 o2 = pack2(1.0f - c0, 1.0f - c1);
        const u64* d = j2 + i * 30;

        u64 M[9];
        #pragma unroll
        for (int k = 0; k < 9; k++)
            M[k] = fma2(o2, d[18 + k], fma2(s2, d[9 + k], d[k]));

        u64 R[9];
        #pragma unroll
        for (int r = 0; r < 3; r++)
            #pragma unroll
            for (int c2i = 0; c2i < 3; c2i++)
                R[r * 3 + c2i] = fma2(Tr[r * 3 + 2], M[6 + c2i],
                                 fma2(Tr[r * 3 + 1], M[3 + c2i],
                                 mul2(Tr[r * 3 + 0], M[0 + c2i])));

        #pragma unroll
        for (int r = 0; r < 3; r++)
            Tt[r] = fma2(Tr[r * 3 + 2], d[29],
                    fma2(Tr[r * 3 + 1], d[28],
                    fma2(Tr[r * 3 + 0], d[27], Tt[r])));

        #pragma unroll
        for (int k = 0; k < 9; k++) Tr[k] = R[k];
    }

    // final: T = T @ F7
    u64 Rr[9], Ot[3];
    #pragma unroll
    for (int r = 0; r < 3; r++) {
        #pragma unroll
        for (int c2i = 0; c2i < 3; c2i++)
            Rr[r * 3 + c2i] = fma2(Tr[r * 3 + 2], F2[8 + c2i],
                              fma2(Tr[r * 3 + 1], F2[4 + c2i],
                              mul2(Tr[r * 3 + 0], F2[0 + c2i])));
        Ot[r] = fma2(Tr[r * 3 + 2], F2[11],
                fma2(Tr[r * 3 + 1], F2[7],
                fma2(Tr[r * 3 + 0], F2[3], Tt[r])));
    }

    // unpack and store both elements (R1-style 4x STG.128 each)
    float2 rr[9], ot[3];
    #pragma unroll
    for (int k = 0; k < 9; k++) rr[k] = unpack2(Rr[k]);
    #pragma unroll
    for (int k = 0; k < 3; k++) ot[k] = unpack2(Ot[k]);

    {
        float4* o0 = reinterpret_cast<float4*>(out + (size_t)g * 16);
        o0[0] = make_float4(rr[0].x, rr[1].x, rr[2].x, ot[0].x);
        o0[1] = make_float4(rr[3].x, rr[4].x, rr[5].x, ot[1].x);
        o0[2] = make_float4(rr[6].x, rr[7].x, rr[8].x, ot[2].x);
        o0[3] = make_float4(0.0f, 0.0f, 0.0f, 1.0f);

        float4* o1 = reinterpret_cast<float4*>(out + (size_t)(g + half) * 16);
        o1[0] = make_float4(rr[0].y, rr[1].y, rr[2].y, ot[0].y);
        o1[1] = make_float4(rr[3].y, rr[4].y, rr[5].y, ot[1].y);
        o1[2] = make_float4(rr[6].y, rr[7].y, rr[8].y, ot[2].y);
        o1[3] = make_float4(0.0f, 0.0f, 0.0f, 1.0f);
    }
}

extern "C" void kernel_launch(void* const* d_in, const int* in_sizes, int n_in,
                              void* d_out, int out_size) {
    const float* jp   = (const float*)d_in[0];  // joint_positions (B,7)
    const float* ft   = (const float*)d_in[1];  // fixed_transforms (8,4,4)
    const float* axes = (const float*)d_in[2];  // joint_axes (7,3)
    float* out = (float*)d_out;
    const int n = in_sizes[0] / NACT;
    const int half = n >> 1;                    // B is even
    const int blocks = (half + THREADS - 1) / THREADS;
    fk_kernel<<<blocks, THREADS>>>(jp, ft, axes, out, n);
}